// round 3
// baseline (speedup 1.0000x reference)
#include <cuda_runtime.h>
#include <math.h>

#define BB 2
#define NTOK 8192
#define DIMX 512
#define NH 8
#define DH 64
#define ML 256
#define BHN 16

__device__ float g_xn[BB*NTOK*DIMX];
__device__ float g_q [BHN*NTOK*DH];
__device__ float g_k [BHN*NTOK*DH];
__device__ float g_v [BHN*NTOK*DH];
__device__ float g_ql[BHN*ML*DH];
__device__ float g_kl[BHN*ML*DH];
__device__ float g_a2[BHN*ML*ML];
__device__ float g_z0[BHN*ML*ML];
__device__ float g_z1[BHN*ML*ML];
__device__ float g_xz[BHN*ML*ML];
__device__ float g_t1[BHN*ML*ML];
__device__ float g_t2[BHN*ML*ML];
__device__ float g_sim3[(size_t)BHN*ML*NTOK];
__device__ float g_a3vp[8*BHN*ML*DH];
__device__ float g_a3v [BHN*ML*DH];
__device__ float g_Z2  [BHN*ML*DH];
__device__ float g_attn[BB*NTOK*DIMX];
__device__ float g_scal[2];

__device__ __forceinline__ void tile_fma32(const float (*As)[65], const float (*Bs)[65],
                                           float acc[4][4], int tx, int ty){
    #pragma unroll
    for(int kk=0;kk<32;kk++){
        float a[4], b[4];
        #pragma unroll
        for(int i=0;i<4;i++) a[i]=As[kk][ty*4+i];
        #pragma unroll
        for(int j=0;j<4;j++) b[j]=Bs[kk][tx+16*j];
        #pragma unroll
        for(int i=0;i<4;i++)
            #pragma unroll
            for(int j=0;j<4;j++) acc[i][j]+=a[i]*b[j];
    }
}

// ---- 1. LayerNorm ----
__global__ void ln_kernel(const float* __restrict__ x, const float* __restrict__ w,
                          const float* __restrict__ bp){
    int row=blockIdx.x, t=threadIdx.x;
    const float* xr = x + (size_t)row*DIMX;
    float v0=xr[t], v1=xr[t+256];
    float s=v0+v1, sq=v0*v0+v1*v1;
    __shared__ float r1[8], r2[8];
    #pragma unroll
    for(int o=16;o;o>>=1){ s+=__shfl_xor_sync(~0u,s,o); sq+=__shfl_xor_sync(~0u,sq,o); }
    if((t&31)==0){ r1[t>>5]=s; r2[t>>5]=sq; }
    __syncthreads();
    float ss=0, qq=0;
    #pragma unroll
    for(int i=0;i<8;i++){ ss+=r1[i]; qq+=r2[i]; }
    float mean=ss*(1.f/512.f);
    float rstd=rsqrtf(qq*(1.f/512.f)-mean*mean+1e-5f);
    g_xn[(size_t)row*DIMX+t]     = (v0-mean)*rstd*w[t]+bp[t];
    g_xn[(size_t)row*DIMX+t+256] = (v1-mean)*rstd*w[t+256]+bp[t+256];
}

// ---- 2. QKV GEMM ----
__global__ void qkv_kernel(const float* __restrict__ W){
    __shared__ float As[32][65], Bs[32][65];
    int t=threadIdx.x, tx=t&15, ty=t>>4;
    int bn=blockIdx.x*64, bm=blockIdx.y*64;
    float acc[4][4]={};
    for(int k0=0;k0<DIMX;k0+=32){
        #pragma unroll
        for(int i=0;i<8;i++){ int idx=t+(i<<8); int r=idx>>5,kk=idx&31;
            As[kk][r]=g_xn[(size_t)(bm+r)*DIMX+k0+kk]; }
        #pragma unroll
        for(int i=0;i<8;i++){ int idx=t+(i<<8); int kk=idx>>6,c=idx&63;
            Bs[kk][c]=W[(size_t)(k0+kk)*1536+bn+c]; }
        __syncthreads();
        tile_fma32(As,Bs,acc,tx,ty);
        __syncthreads();
    }
    #pragma unroll
    for(int i=0;i<4;i++){
        int row=bm+ty*4+i; int b_=row>>13, n=row&8191;
        #pragma unroll
        for(int j=0;j<4;j++){
            int col=bn+tx+(j<<4); int s=col>>9, inner=col&511;
            int h=inner>>6, d=inner&63;
            size_t o=((size_t)((b_*NH+h)*NTOK+n))*DH+d;
            float val=acc[i][j];
            if(s==0) g_q[o]=val*0.125f;
            else if(s==1) g_k[o]=val;
            else g_v[o]=val;
        }
    }
}

// ---- 3. Landmarks ----
__global__ void landmark_kernel(){
    int blk=blockIdx.x, bh=blk>>8, m=blk&255, d=threadIdx.x;
    const float* qp=g_q+((size_t)(bh*NTOK+m*32))*DH+d;
    const float* kp=g_k+((size_t)(bh*NTOK+m*32))*DH+d;
    float sq=0,sk=0;
    #pragma unroll
    for(int j=0;j<32;j++){ sq+=qp[(size_t)j*DH]; sk+=kp[(size_t)j*DH]; }
    g_ql[(bh*ML+m)*DH+d]=sq*(1.f/32.f);
    g_kl[(bh*ML+m)*DH+d]=sk*(1.f/32.f);
}

// ---- 4. a2 = softmax(ql @ kl^T) ----
__global__ void a2_kernel(){
    int bh=blockIdx.x, t=threadIdx.x;
    float klr[64];
    #pragma unroll
    for(int kk=0;kk<64;kk++) klr[kk]=g_kl[(bh*ML+t)*DH+kk];
    __shared__ float qs[64];
    __shared__ float red[8];
    for(int i=0;i<ML;i++){
        if(t<64) qs[t]=g_ql[(bh*ML+i)*DH+t];
        __syncthreads();
        float dot=0;
        #pragma unroll
        for(int kk=0;kk<64;kk++) dot+=klr[kk]*qs[kk];
        float m=dot;
        #pragma unroll
        for(int o=16;o;o>>=1) m=fmaxf(m,__shfl_xor_sync(~0u,m,o));
        if((t&31)==0) red[t>>5]=m;
        __syncthreads();
        m=red[0];
        #pragma unroll
        for(int k=1;k<8;k++) m=fmaxf(m,red[k]);
        float e=__expf(dot-m), s=e;
        #pragma unroll
        for(int o=16;o;o>>=1) s+=__shfl_xor_sync(~0u,s,o);
        __syncthreads();
        if((t&31)==0) red[t>>5]=s;
        __syncthreads();
        s=0;
        #pragma unroll
        for(int k=0;k<8;k++) s+=red[k];
        g_a2[(size_t)(bh*ML+i)*ML+t]=e/s;
        __syncthreads();
    }
}

// ---- 5. pinv init ----
__global__ void scal_reset_kernel(){ g_scal[0]=0.f; g_scal[1]=0.f; }

__global__ void pinv_sums_kernel(){
    int bh=blockIdx.x, t=threadIdx.x;
    const float* A=g_a2+((size_t)bh<<16);
    float rs=0, cs=0;
    for(int j=0;j<ML;j++){ rs+=fabsf(A[(size_t)t*ML+j]); cs+=fabsf(A[(size_t)j*ML+t]); }
    #pragma unroll
    for(int o=16;o;o>>=1){ rs=fmaxf(rs,__shfl_xor_sync(~0u,rs,o)); cs=fmaxf(cs,__shfl_xor_sync(~0u,cs,o)); }
    __shared__ float r1[8], r2[8];
    if((t&31)==0){ r1[t>>5]=rs; r2[t>>5]=cs; }
    __syncthreads();
    if(t==0){
        float m1=r1[0], m2=r2[0];
        #pragma unroll
        for(int k=1;k<8;k++){ m1=fmaxf(m1,r1[k]); m2=fmaxf(m2,r2[k]); }
        atomicMax((int*)&g_scal[0], __float_as_int(m1));
        atomicMax((int*)&g_scal[1], __float_as_int(m2));
    }
}

__global__ void zinit_kernel(){
    int e=blockIdx.x*256+threadIdx.x;
    float inv=1.f/(g_scal[0]*g_scal[1]);
    int bh=e>>16, r=(e>>8)&255, c=e&255;
    g_z0[e]=g_a2[(bh<<16)+(c<<8)+r]*inv;
}

// ---- 6. batched 256^3: C = alpha * A @ (cdiag*I - B) ----
__global__ void mm256_kernel(const float* __restrict__ Ag, const float* __restrict__ Bg,
                             float* __restrict__ Cg, float cdiag, float alpha){
    int bh=blockIdx.x;
    const float* A=Ag+((size_t)bh<<16);
    const float* B=Bg+((size_t)bh<<16);
    float* C=Cg+((size_t)bh<<16);
    int bm=blockIdx.y*64, bn=blockIdx.z*64;
    __shared__ float As[32][65], Bs[32][65];
    int t=threadIdx.x, tx=t&15, ty=t>>4;
    float acc[4][4]={};
    for(int k0=0;k0<256;k0+=32){
        #pragma unroll
        for(int i=0;i<8;i++){ int idx=t+(i<<8); int r=idx>>5,kk=idx&31;
            As[kk][r]=A[(size_t)(bm+r)*256+k0+kk]; }
        #pragma unroll
        for(int i=0;i<8;i++){ int idx=t+(i<<8); int kk=idx>>6,c=idx&63;
            int gk=k0+kk, gc=bn+c;
            float bv=B[(size_t)gk*256+gc];
            Bs[kk][c]=(gk==gc)?(cdiag-bv):(-bv); }
        __syncthreads();
        tile_fma32(As,Bs,acc,tx,ty);
        __syncthreads();
    }
    #pragma unroll
    for(int i=0;i<4;i++)
        #pragma unroll
        for(int j=0;j<4;j++)
            C[(size_t)(bm+ty*4+i)*256+bn+tx+(j<<4)]=alpha*acc[i][j];
}

// ---- 7a. sim3 = ql @ k^T ----
__global__ void sim3_kernel(){
    int bh=blockIdx.z, bn=blockIdx.x*64, bm=blockIdx.y*64;
    __shared__ float As[64][65], Bs[64][65];
    int t=threadIdx.x, tx=t&15, ty=t>>4;
    const float* qlp=g_ql+bh*ML*DH;
    const float* kp=g_k+(size_t)bh*NTOK*DH;
    #pragma unroll
    for(int i=0;i<16;i++){ int idx=t+(i<<8); int r=idx>>6,kk=idx&63;
        As[kk][r]=qlp[(bm+r)*DH+kk];
        Bs[kk][r]=kp[(size_t)(bn+r)*DH+kk]; }
    __syncthreads();
    float acc[4][4]={};
    #pragma unroll
    for(int kk=0;kk<64;kk++){
        float a[4], b[4];
        #pragma unroll
        for(int i=0;i<4;i++) a[i]=As[kk][ty*4+i];
        #pragma unroll
        for(int j=0;j<4;j++) b[j]=Bs[kk][tx+16*j];
        #pragma unroll
        for(int i=0;i<4;i++)
            #pragma unroll
            for(int j=0;j<4;j++) acc[i][j]+=a[i]*b[j];
    }
    #pragma unroll
    for(int i=0;i<4;i++)
        #pragma unroll
        for(int j=0;j<4;j++)
            g_sim3[(size_t)(bh*ML+bm+ty*4+i)*NTOK+bn+tx+(j<<4)]=acc[i][j];
}

// ---- 7b. softmax rows of 8192 ----
__global__ void softmax3_kernel(){
    int row=blockIdx.x, t=threadIdx.x;
    float* p=g_sim3+(size_t)row*NTOK;
    float v[32], mx=-3.0e38f;
    #pragma unroll
    for(int i=0;i<32;i++){ v[i]=p[t+(i<<8)]; mx=fmaxf(mx,v[i]); }
    __shared__ float red[8];
    #pragma unroll
    for(int o=16;o;o>>=1) mx=fmaxf(mx,__shfl_xor_sync(~0u,mx,o));
    if((t&31)==0) red[t>>5]=mx;
    __syncthreads();
    mx=red[0];
    #pragma unroll
    for(int k=1;k<8;k++) mx=fmaxf(mx,red[k]);
    float s=0;
    #pragma unroll
    for(int i=0;i<32;i++){ v[i]=__expf(v[i]-mx); s+=v[i]; }
    #pragma unroll
    for(int o=16;o;o>>=1) s+=__shfl_xor_sync(~0u,s,o);
    __syncthreads();
    if((t&31)==0) red[t>>5]=s;
    __syncthreads();
    s=0;
    #pragma unroll
    for(int k=0;k<8;k++) s+=red[k];
    float inv=1.f/s;
    #pragma unroll
    for(int i=0;i<32;i++) p[t+(i<<8)]=v[i]*inv;
}

// ---- 7c. a3 @ v split-K ----
__global__ void a3v_kernel(){
    int ksp=blockIdx.x, bm=blockIdx.y*64, bh=blockIdx.z;
    __shared__ float As[32][65], Bs[32][65];
    int t=threadIdx.x, tx=t&15, ty=t>>4;
    float acc[4][4]={};
    const float* Ap=g_sim3+(size_t)(bh*ML)*NTOK;
    const float* Vp=g_v+(size_t)bh*NTOK*DH;
    int kbeg=ksp*1024;
    for(int k0=kbeg;k0<kbeg+1024;k0+=32){
        #pragma unroll
        for(int i=0;i<8;i++){ int idx=t+(i<<8); int r=idx>>5,kk=idx&31;
            As[kk][r]=Ap[(size_t)(bm+r)*NTOK+k0+kk]; }
        #pragma unroll
        for(int i=0;i<8;i++){ int idx=t+(i<<8); int kk=idx>>6,c=idx&63;
            Bs[kk][c]=Vp[(size_t)(k0+kk)*DH+c]; }
        __syncthreads();
        tile_fma32(As,Bs,acc,tx,ty);
        __syncthreads();
    }
    #pragma unroll
    for(int i=0;i<4;i++)
        #pragma unroll
        for(int j=0;j<4;j++)
            g_a3vp[(size_t)(ksp*BHN+bh)*ML*DH+(bm+ty*4+i)*DH+tx+(j<<4)]=acc[i][j];
}

__global__ void a3v_reduce_kernel(){
    int e=blockIdx.x*256+threadIdx.x;
    float s=0;
    #pragma unroll
    for(int k=0;k<8;k++) s+=g_a3vp[(size_t)k*BHN*ML*DH+e];
    g_a3v[e]=s;
}

// ---- 8. Z2 = z_final @ a3v ----
__global__ void z2_kernel(){
    int bh=blockIdx.x, bm=blockIdx.y*64;
    const float* A=g_z0+((size_t)bh<<16);
    const float* Bp=g_a3v+bh*ML*DH;
    __shared__ float As[32][65], Bs[32][65];
    int t=threadIdx.x, tx=t&15, ty=t>>4;
    float acc[4][4]={};
    for(int k0=0;k0<256;k0+=32){
        #pragma unroll
        for(int i=0;i<8;i++){ int idx=t+(i<<8); int r=idx>>5,kk=idx&31;
            As[kk][r]=A[(size_t)(bm+r)*256+k0+kk]; }
        #pragma unroll
        for(int i=0;i<8;i++){ int idx=t+(i<<8); int kk=idx>>6,c=idx&63;
            Bs[kk][c]=Bp[(k0+kk)*DH+c]; }
        __syncthreads();
        tile_fma32(As,Bs,acc,tx,ty);
        __syncthreads();
    }
    #pragma unroll
    for(int i=0;i<4;i++)
        #pragma unroll
        for(int j=0;j<4;j++)
            g_Z2[bh*ML*DH+(bm+ty*4+i)*DH+tx+(j<<4)]=acc[i][j];
}

// ---- 9. depthwise conv residual (writes g_attn) ----
__global__ void conv_kernel(const float* __restrict__ cw){
    int idx=blockIdx.x*256+threadIdx.x;
    int d=idx&63, n=(idx>>6)&8191, bh=idx>>19;
    int h=bh&7;
    const float* vp=g_v+(size_t)bh*NTOK*DH+d;
    float s=0;
    #pragma unroll
    for(int kk=0;kk<33;kk++){
        int j=n+kk-16;
        if(j>=0 && j<NTOK) s+=cw[h*33+kk]*vp[(size_t)j*DH];
    }
    g_attn[((size_t)((bh>>3)*NTOK+n))*DIMX+h*64+d]=s;
}

// ---- 10. fused a1 = softmax(q@kl^T) @ Z2, += into g_attn ----
__global__ void a1_kernel(){
    __shared__ float qsm[16][68];
    __shared__ float tile[64][68];
    __shared__ float sims[16][260];
    int t=threadIdx.x;
    int tt=blockIdx.x; int bh=tt>>9; int n0=(tt&511)*16;
    const float* qp=g_q+((size_t)(bh*NTOK+n0))*DH;
    for(int i=t;i<16*64;i+=256){ int r=i>>6,d=i&63; qsm[r][d]=qp[(size_t)r*DH+d]; }
    int row=t>>4, j4=t&15;
    for(int c=0;c<4;c++){
        const float* klp=g_kl+(bh*ML+c*64)*DH;
        __syncthreads();
        for(int i=t;i<64*64;i+=256){ int r=i>>6,d=i&63; tile[r][d]=klp[r*64+d]; }
        __syncthreads();
        #pragma unroll
        for(int l=0;l<4;l++){
            int lm=j4+l*16;
            float s=0;
            #pragma unroll
            for(int kk=0;kk<64;kk++) s+=qsm[row][kk]*tile[lm][kk];
            sims[row][c*64+lm]=s;
        }
    }
    __syncthreads();
    int w=t>>5, lane=t&31;
    for(int rr=w*2; rr<w*2+2; rr++){
        float mx=-3e38f;
        #pragma unroll
        for(int i=0;i<8;i++) mx=fmaxf(mx,sims[rr][lane+32*i]);
        #pragma unroll
        for(int o=16;o;o>>=1) mx=fmaxf(mx,__shfl_xor_sync(~0u,mx,o));
        float e[8], sum=0;
        #pragma unroll
        for(int i=0;i<8;i++){ e[i]=__expf(sims[rr][lane+32*i]-mx); sum+=e[i]; }
        #pragma unroll
        for(int o=16;o;o>>=1) sum+=__shfl_xor_sync(~0u,sum,o);
        float inv=1.f/sum;
        #pragma unroll
        for(int i=0;i<8;i++) sims[rr][lane+32*i]=e[i]*inv;
    }
    float acc[4]={0,0,0,0};
    for(int c=0;c<4;c++){
        const float* zp=g_Z2+(bh*ML+c*64)*DH;
        __syncthreads();
        for(int i=t;i<64*64;i+=256){ int r=i>>6,d=i&63; tile[r][d]=zp[r*64+d]; }
        __syncthreads();
        for(int lm=0;lm<64;lm++){
            float a=sims[row][c*64+lm];
            #pragma unroll
            for(int j=0;j<4;j++) acc[j]+=a*tile[lm][j4+16*j];
        }
    }
    int b=bh>>3, h=bh&7;
    size_t base=((size_t)(b*NTOK+n0+row))*DIMX+h*64;
    #pragma unroll
    for(int j=0;j<4;j++) g_attn[base+j4+16*j]+=acc[j];
}

// ---- 11. out = x + attn @ w_out + b_out ----
__global__ void out_kernel(const float* __restrict__ W, const float* __restrict__ bias,
                           const float* __restrict__ x, float* __restrict__ out){
    __shared__ float As[32][65], Bs[32][65];
    int t=threadIdx.x, tx=t&15, ty=t>>4;
    int bn=blockIdx.x*64, bm=blockIdx.y*64;
    float acc[4][4]={};
    for(int k0=0;k0<512;k0+=32){
        #pragma unroll
        for(int i=0;i<8;i++){ int idx=t+(i<<8); int r=idx>>5,kk=idx&31;
            As[kk][r]=g_attn[(size_t)(bm+r)*DIMX+k0+kk]; }
        #pragma unroll
        for(int i=0;i<8;i++){ int idx=t+(i<<8); int kk=idx>>6,c=idx&63;
            Bs[kk][c]=W[(size_t)(k0+kk)*DIMX+bn+c]; }
        __syncthreads();
        tile_fma32(As,Bs,acc,tx,ty);
        __syncthreads();
    }
    #pragma unroll
    for(int i=0;i<4;i++){
        size_t r=(size_t)(bm+ty*4+i)*DIMX;
        #pragma unroll
        for(int j=0;j<4;j++){
            int col=bn+tx+(j<<4);
            out[r+col]=x[r+col]+bias[col]+acc[i][j];
        }
    }
}

extern "C" void kernel_launch(void* const* d_in, const int* in_sizes, int n_in,
                              void* d_out, int out_size){
    const float* x    = (const float*)d_in[0];
    const float* ln_w = (const float*)d_in[2];
    const float* ln_b = (const float*)d_in[3];
    const float* wqkv = (const float*)d_in[4];
    const float* wout = (const float*)d_in[5];
    const float* bout = (const float*)d_in[6];
    const float* cw   = (const float*)d_in[7];
    float* out = (float*)d_out;

    float *z0, *z1, *a2, *xz, *t1, *t2;
    cudaGetSymbolAddress((void**)&z0, g_z0);
    cudaGetSymbolAddress((void**)&z1, g_z1);
    cudaGetSymbolAddress((void**)&a2, g_a2);
    cudaGetSymbolAddress((void**)&xz, g_xz);
    cudaGetSymbolAddress((void**)&t1, g_t1);
    cudaGetSymbolAddress((void**)&t2, g_t2);

    ln_kernel<<<BB*NTOK, 256>>>(x, ln_w, ln_b);
    qkv_kernel<<<dim3(24,256), 256>>>(wqkv);
    landmark_kernel<<<BHN*ML, 64>>>();
    a2_kernel<<<BHN, 256>>>();
    scal_reset_kernel<<<1,1>>>();
    pinv_sums_kernel<<<BHN, 256>>>();
    zinit_kernel<<<4096, 256>>>();

    float* zc=z0; float* za=z1;
    for(int it=0; it<6; it++){
        mm256_kernel<<<dim3(BHN,4,4),256>>>(a2, zc, xz, 0.f, -1.f);   // xz = a2@z
        mm256_kernel<<<dim3(BHN,4,4),256>>>(xz, xz, t1, 7.f, 1.f);    // t1 = xz@(7I-xz)
        mm256_kernel<<<dim3(BHN,4,4),256>>>(xz, t1, t2, 15.f, 1.f);   // t2 = xz@(15I-t1)
        mm256_kernel<<<dim3(BHN,4,4),256>>>(zc, t2, za, 13.f, 0.25f); // z = .25 z@(13I-t2)
        float* tmp=zc; zc=za; za=tmp;
    }
    // zc == z0 after 6 swaps

    sim3_kernel<<<dim3(128,4,BHN), 256>>>();
    softmax3_kernel<<<BHN*ML, 256>>>();
    a3v_kernel<<<dim3(8,4,BHN), 256>>>();
    a3v_reduce_kernel<<<1024, 256>>>();
    z2_kernel<<<dim3(BHN,4), 256>>>();
    conv_kernel<<<32768, 256>>>(cw);
    a1_kernel<<<8192, 256>>>();
    out_kernel<<<dim3(8,256), 256>>>(wout, bout, x, out);
}

// round 4
// speedup vs baseline: 1.3636x; 1.3636x over previous
#include <cuda_runtime.h>
#include <math.h>

#define BB 2
#define NTOK 8192
#define DIMX 512
#define NH 8
#define DH 64
#define ML 256
#define BHN 16

__device__ float g_xn[BB*NTOK*DIMX];
__device__ float g_q [BHN*NTOK*DH];
__device__ float g_k [BHN*NTOK*DH];
__device__ float g_v [BHN*NTOK*DH];
__device__ float g_ql[BHN*ML*DH];
__device__ float g_kl[BHN*ML*DH];
__device__ float g_a2[BHN*ML*ML];
__device__ float g_z0[BHN*ML*ML];
__device__ float g_z1[BHN*ML*ML];
__device__ float g_xz[BHN*ML*ML];
__device__ float g_t1[BHN*ML*ML];
__device__ float g_t2[BHN*ML*ML];
__device__ float g_sim3[(size_t)BHN*ML*NTOK];
__device__ float g_a3vp[8*BHN*ML*DH];
__device__ float g_a3v [BHN*ML*DH];
__device__ float g_Z2  [BHN*ML*DH];
__device__ float g_attn[BB*NTOK*DIMX];
__device__ float g_scal[2];

// ================= shared-memory GEMM cores =================
// [kk][col] layout with odd stride 129/65 -> conflict-free scalar access.

__device__ __forceinline__ void loadA_kmajor(float (*As)[129], const float* __restrict__ Ag,
                                             int lda, int bm, int k0, int t){
    // 128 rows x 32 kk, float4 along k
    #pragma unroll
    for(int i=0;i<4;i++){
        int q=t+(i<<8); int r=q>>3; int kq=q&7;
        float4 v=*(const float4*)(Ag+(size_t)(bm+r)*lda+k0+(kq<<2));
        As[(kq<<2)+0][r]=v.x; As[(kq<<2)+1][r]=v.y;
        As[(kq<<2)+2][r]=v.z; As[(kq<<2)+3][r]=v.w;
    }
}
__device__ __forceinline__ void loadB_kn128(float (*Bs)[129], const float* __restrict__ Bg,
                                            int ldb, int bn, int k0, int t){
    // 32 kk x 128 cols, float4 along n
    #pragma unroll
    for(int i=0;i<4;i++){
        int q=t+(i<<8); int kk=q>>5; int cq=q&31;
        float4 v=*(const float4*)(Bg+(size_t)(k0+kk)*ldb+bn+(cq<<2));
        Bs[kk][(cq<<2)+0]=v.x; Bs[kk][(cq<<2)+1]=v.y;
        Bs[kk][(cq<<2)+2]=v.z; Bs[kk][(cq<<2)+3]=v.w;
    }
}
__device__ __forceinline__ void loadB_kn64(float (*Bs)[65], const float* __restrict__ Bg,
                                           int ldb, int bn, int k0, int t){
    #pragma unroll
    for(int i=0;i<2;i++){
        int q=t+(i<<8); int kk=q>>4; int cq=q&15;
        float4 v=*(const float4*)(Bg+(size_t)(k0+kk)*ldb+bn+(cq<<2));
        Bs[kk][(cq<<2)+0]=v.x; Bs[kk][(cq<<2)+1]=v.y;
        Bs[kk][(cq<<2)+2]=v.z; Bs[kk][(cq<<2)+3]=v.w;
    }
}
__device__ __forceinline__ void fma128(const float (*As)[129], const float (*Bs)[129],
                                       float acc[8][8], int tx, int ty){
    #pragma unroll
    for(int kk=0;kk<32;kk++){
        float a[8], b[8];
        #pragma unroll
        for(int i=0;i<8;i++) a[i]=As[kk][ty*8+i];
        #pragma unroll
        for(int j=0;j<8;j++) b[j]=Bs[kk][tx+(j<<4)];
        #pragma unroll
        for(int i=0;i<8;i++)
            #pragma unroll
            for(int j=0;j<8;j++) acc[i][j]+=a[i]*b[j];
    }
}
__device__ __forceinline__ void fma64(const float (*As)[129], const float (*Bs)[65],
                                      float acc[8][4], int tx, int ty){
    #pragma unroll
    for(int kk=0;kk<32;kk++){
        float a[8], b[4];
        #pragma unroll
        for(int i=0;i<8;i++) a[i]=As[kk][ty*8+i];
        #pragma unroll
        for(int j=0;j<4;j++) b[j]=Bs[kk][tx+(j<<4)];
        #pragma unroll
        for(int i=0;i<8;i++)
            #pragma unroll
            for(int j=0;j<4;j++) acc[i][j]+=a[i]*b[j];
    }
}
// small 64x64 core (kept for mm256)
__device__ __forceinline__ void tile_fma32(const float (*As)[65], const float (*Bs)[65],
                                           float acc[4][4], int tx, int ty){
    #pragma unroll
    for(int kk=0;kk<32;kk++){
        float a[4], b[4];
        #pragma unroll
        for(int i=0;i<4;i++) a[i]=As[kk][ty*4+i];
        #pragma unroll
        for(int j=0;j<4;j++) b[j]=Bs[kk][tx+16*j];
        #pragma unroll
        for(int i=0;i<4;i++)
            #pragma unroll
            for(int j=0;j<4;j++) acc[i][j]+=a[i]*b[j];
    }
}

// ---- 1. LayerNorm ----
__global__ void ln_kernel(const float* __restrict__ x, const float* __restrict__ w,
                          const float* __restrict__ bp){
    int row=blockIdx.x, t=threadIdx.x;
    const float* xr = x + (size_t)row*DIMX;
    float v0=xr[t], v1=xr[t+256];
    float s=v0+v1, sq=v0*v0+v1*v1;
    __shared__ float r1[8], r2[8];
    #pragma unroll
    for(int o=16;o;o>>=1){ s+=__shfl_xor_sync(~0u,s,o); sq+=__shfl_xor_sync(~0u,sq,o); }
    if((t&31)==0){ r1[t>>5]=s; r2[t>>5]=sq; }
    __syncthreads();
    float ss=0, qq=0;
    #pragma unroll
    for(int i=0;i<8;i++){ ss+=r1[i]; qq+=r2[i]; }
    float mean=ss*(1.f/512.f);
    float rstd=rsqrtf(qq*(1.f/512.f)-mean*mean+1e-5f);
    g_xn[(size_t)row*DIMX+t]     = (v0-mean)*rstd*w[t]+bp[t];
    g_xn[(size_t)row*DIMX+t+256] = (v1-mean)*rstd*w[t+256]+bp[t+256];
}

// ---- 2. QKV GEMM 128x128 ----
__global__ void qkv_kernel(const float* __restrict__ W){
    __shared__ float As[32][129], Bs[32][129];
    int t=threadIdx.x, tx=t&15, ty=t>>4;
    int bn=blockIdx.x*128, bm=blockIdx.y*128;
    float acc[8][8]={};
    for(int k0=0;k0<DIMX;k0+=32){
        loadA_kmajor(As, g_xn, DIMX, bm, k0, t);
        loadB_kn128(Bs, W, 1536, bn, k0, t);
        __syncthreads();
        fma128(As,Bs,acc,tx,ty);
        __syncthreads();
    }
    #pragma unroll
    for(int i=0;i<8;i++){
        int row=bm+ty*8+i; int b_=row>>13, n=row&8191;
        #pragma unroll
        for(int j=0;j<8;j++){
            int col=bn+tx+(j<<4); int s=col>>9, inner=col&511;
            int h=inner>>6, d=inner&63;
            size_t o=((size_t)((b_*NH+h)*NTOK+n))*DH+d;
            float val=acc[i][j];
            if(s==0) g_q[o]=val*0.125f;
            else if(s==1) g_k[o]=val;
            else g_v[o]=val;
        }
    }
}

// ---- 3. Landmarks ----
__global__ void landmark_kernel(){
    int blk=blockIdx.x, bh=blk>>8, m=blk&255, d=threadIdx.x;
    const float* qp=g_q+((size_t)(bh*NTOK+m*32))*DH+d;
    const float* kp=g_k+((size_t)(bh*NTOK+m*32))*DH+d;
    float sq=0,sk=0;
    #pragma unroll
    for(int j=0;j<32;j++){ sq+=qp[(size_t)j*DH]; sk+=kp[(size_t)j*DH]; }
    g_ql[(bh*ML+m)*DH+d]=sq*(1.f/32.f);
    g_kl[(bh*ML+m)*DH+d]=sk*(1.f/32.f);
}

// ---- 4. a2 = softmax(ql @ kl^T), parallel: grid(BHN,32), 8 rows/block ----
__global__ void a2_kernel(){
    int bh=blockIdx.x, t=threadIdx.x;
    __shared__ float qs[64];
    __shared__ float red[8];
    const float4* klp=(const float4*)(g_kl+(size_t)bh*ML*DH) + (size_t)t*16;
    for(int rr=0;rr<8;rr++){
        int i=blockIdx.y*8+rr;
        if(t<16) ((float4*)qs)[t]=((const float4*)(g_ql+(size_t)(bh*ML+i)*DH))[t];
        __syncthreads();
        float dot=0;
        #pragma unroll
        for(int kq=0;kq<16;kq++){
            float4 kv=klp[kq];
            dot+=kv.x*qs[kq*4]+kv.y*qs[kq*4+1]+kv.z*qs[kq*4+2]+kv.w*qs[kq*4+3];
        }
        float m=dot;
        #pragma unroll
        for(int o=16;o;o>>=1) m=fmaxf(m,__shfl_xor_sync(~0u,m,o));
        if((t&31)==0) red[t>>5]=m;
        __syncthreads();
        m=red[0];
        #pragma unroll
        for(int k=1;k<8;k++) m=fmaxf(m,red[k]);
        float e=__expf(dot-m), s=e;
        #pragma unroll
        for(int o=16;o;o>>=1) s+=__shfl_xor_sync(~0u,s,o);
        __syncthreads();
        if((t&31)==0) red[t>>5]=s;
        __syncthreads();
        s=0;
        #pragma unroll
        for(int k=0;k<8;k++) s+=red[k];
        g_a2[(size_t)(bh*ML+i)*ML+t]=e/s;
        __syncthreads();
    }
}

// ---- 5. pinv init ----
__global__ void scal_reset_kernel(){ g_scal[0]=0.f; g_scal[1]=0.f; }

__global__ void pinv_sums_kernel(){
    int bh=blockIdx.x, t=threadIdx.x;
    const float* A=g_a2+((size_t)bh<<16);
    float rs=0, cs=0;
    const float4* Ar=(const float4*)(A+(size_t)t*ML);
    #pragma unroll
    for(int j=0;j<64;j++){ float4 v=Ar[j]; rs+=fabsf(v.x)+fabsf(v.y)+fabsf(v.z)+fabsf(v.w); }
    for(int j=0;j<ML;j++) cs+=fabsf(A[(size_t)j*ML+t]);
    #pragma unroll
    for(int o=16;o;o>>=1){ rs=fmaxf(rs,__shfl_xor_sync(~0u,rs,o)); cs=fmaxf(cs,__shfl_xor_sync(~0u,cs,o)); }
    __shared__ float r1[8], r2[8];
    if((t&31)==0){ r1[t>>5]=rs; r2[t>>5]=cs; }
    __syncthreads();
    if(t==0){
        float m1=r1[0], m2=r2[0];
        #pragma unroll
        for(int k=1;k<8;k++){ m1=fmaxf(m1,r1[k]); m2=fmaxf(m2,r2[k]); }
        atomicMax((int*)&g_scal[0], __float_as_int(m1));
        atomicMax((int*)&g_scal[1], __float_as_int(m2));
    }
}

__global__ void zinit_kernel(){
    int e=blockIdx.x*256+threadIdx.x;
    float inv=1.f/(g_scal[0]*g_scal[1]);
    int bh=e>>16, r=(e>>8)&255, c=e&255;
    g_z0[e]=g_a2[(bh<<16)+(c<<8)+r]*inv;
}

// ---- 6. batched 256^3: C = alpha * A @ (cdiag*I - B) ----
__global__ void mm256_kernel(const float* __restrict__ Ag, const float* __restrict__ Bg,
                             float* __restrict__ Cg, float cdiag, float alpha){
    int bh=blockIdx.x;
    const float* A=Ag+((size_t)bh<<16);
    const float* B=Bg+((size_t)bh<<16);
    float* C=Cg+((size_t)bh<<16);
    int bm=blockIdx.y*64, bn=blockIdx.z*64;
    __shared__ float As[32][65], Bs[32][65];
    int t=threadIdx.x, tx=t&15, ty=t>>4;
    float acc[4][4]={};
    for(int k0=0;k0<256;k0+=32){
        #pragma unroll
        for(int i=0;i<8;i++){ int idx=t+(i<<8); int r=idx>>5,kk=idx&31;
            As[kk][r]=A[(size_t)(bm+r)*256+k0+kk]; }
        #pragma unroll
        for(int i=0;i<8;i++){ int idx=t+(i<<8); int kk=idx>>6,c=idx&63;
            int gk=k0+kk, gc=bn+c;
            float bv=B[(size_t)gk*256+gc];
            Bs[kk][c]=(gk==gc)?(cdiag-bv):(-bv); }
        __syncthreads();
        tile_fma32(As,Bs,acc,tx,ty);
        __syncthreads();
    }
    #pragma unroll
    for(int i=0;i<4;i++)
        #pragma unroll
        for(int j=0;j<4;j++)
            C[(size_t)(bm+ty*4+i)*256+bn+tx+(j<<4)]=alpha*acc[i][j];
}

// ---- 7. sim kernel: C[M x N] = A[M x 64] @ B[N x 64]^T (both K-major), per bh ----
__global__ void sim_kernel(const float* __restrict__ Abase, const float* __restrict__ Bbase,
                           float* __restrict__ Cbase, size_t aBH, size_t bBH, size_t cBH, int ldC){
    __shared__ float As[32][129], Bs[32][129];
    int t=threadIdx.x, tx=t&15, ty=t>>4;
    int bh=blockIdx.z;
    int bn=blockIdx.x*128, bm=blockIdx.y*128;
    const float* A=Abase+(size_t)bh*aBH;
    const float* B=Bbase+(size_t)bh*bBH;
    float* C=Cbase+(size_t)bh*cBH;
    float acc[8][8]={};
    for(int k0=0;k0<64;k0+=32){
        loadA_kmajor(As, A, DH, bm, k0, t);
        loadA_kmajor(Bs, B, DH, bn, k0, t);   // B^T tile: cols of C are rows of B
        __syncthreads();
        fma128(As,Bs,acc,tx,ty);
        __syncthreads();
    }
    #pragma unroll
    for(int i=0;i<8;i++)
        #pragma unroll
        for(int j=0;j<8;j++)
            C[(size_t)(bm+ty*8+i)*ldC + bn+tx+(j<<4)]=acc[i][j];
}

// ---- 7b. softmax rows of 8192 ----
__global__ void softmax3_kernel(){
    int row=blockIdx.x, t=threadIdx.x;
    float* p=g_sim3+(size_t)row*NTOK;
    float v[32], mx=-3.0e38f;
    #pragma unroll
    for(int i=0;i<32;i++){ v[i]=p[t+(i<<8)]; mx=fmaxf(mx,v[i]); }
    __shared__ float red[8];
    #pragma unroll
    for(int o=16;o;o>>=1) mx=fmaxf(mx,__shfl_xor_sync(~0u,mx,o));
    if((t&31)==0) red[t>>5]=mx;
    __syncthreads();
    mx=red[0];
    #pragma unroll
    for(int k=1;k<8;k++) mx=fmaxf(mx,red[k]);
    float s=0;
    #pragma unroll
    for(int i=0;i<32;i++){ v[i]=__expf(v[i]-mx); s+=v[i]; }
    #pragma unroll
    for(int o=16;o;o>>=1) s+=__shfl_xor_sync(~0u,s,o);
    __syncthreads();
    if((t&31)==0) red[t>>5]=s;
    __syncthreads();
    s=0;
    #pragma unroll
    for(int k=0;k<8;k++) s+=red[k];
    float inv=1.f/s;
    #pragma unroll
    for(int i=0;i<32;i++) p[t+(i<<8)]=v[i]*inv;
}

// ---- 7c. a3 @ v split-K (128x64 tiles) ----
__global__ void a3v_kernel(){
    __shared__ float As[32][129], Bs[32][65];
    int ksp=blockIdx.x, bm=blockIdx.y*128, bh=blockIdx.z;
    int t=threadIdx.x, tx=t&15, ty=t>>4;
    float acc[8][4]={};
    const float* Ap=g_sim3+(size_t)(bh*ML)*NTOK;
    const float* Vp=g_v+(size_t)bh*NTOK*DH;
    int kbeg=ksp*1024;
    for(int k0=kbeg;k0<kbeg+1024;k0+=32){
        loadA_kmajor(As, Ap, NTOK, bm, k0, t);
        loadB_kn64(Bs, Vp, DH, 0, k0, t);
        __syncthreads();
        fma64(As,Bs,acc,tx,ty);
        __syncthreads();
    }
    #pragma unroll
    for(int i=0;i<8;i++)
        #pragma unroll
        for(int j=0;j<4;j++)
            g_a3vp[(size_t)(ksp*BHN+bh)*ML*DH+(bm+ty*8+i)*DH+tx+(j<<4)]=acc[i][j];
}

__global__ void a3v_reduce_kernel(){
    int e=blockIdx.x*256+threadIdx.x;
    float s=0;
    #pragma unroll
    for(int k=0;k<8;k++) s+=g_a3vp[(size_t)k*BHN*ML*DH+e];
    g_a3v[e]=s;
}

// ---- 8. Z2 = z_final @ a3v (128x64) ----
__global__ void z2_kernel(){
    __shared__ float As[32][129], Bs[32][65];
    int bm=blockIdx.x*128, bh=blockIdx.y;
    const float* A=g_z0+((size_t)bh<<16);
    const float* Bp=g_a3v+(size_t)bh*ML*DH;
    int t=threadIdx.x, tx=t&15, ty=t>>4;
    float acc[8][4]={};
    for(int k0=0;k0<256;k0+=32){
        loadA_kmajor(As, A, ML, bm, k0, t);
        loadB_kn64(Bs, Bp, DH, 0, k0, t);
        __syncthreads();
        fma64(As,Bs,acc,tx,ty);
        __syncthreads();
    }
    #pragma unroll
    for(int i=0;i<8;i++)
        #pragma unroll
        for(int j=0;j<4;j++)
            g_Z2[(size_t)bh*ML*DH+(bm+ty*8+i)*DH+tx+(j<<4)]=acc[i][j];
}

// ---- 9. depthwise conv residual (writes g_attn) ----
__global__ void conv_kernel(const float* __restrict__ cw){
    int idx=blockIdx.x*256+threadIdx.x;
    int d=idx&63, n=(idx>>6)&8191, bh=idx>>19;
    int h=bh&7;
    const float* vp=g_v+(size_t)bh*NTOK*DH+d;
    float s=0;
    #pragma unroll
    for(int kk=0;kk<33;kk++){
        int j=n+kk-16;
        if(j>=0 && j<NTOK) s+=cw[h*33+kk]*vp[(size_t)j*DH];
    }
    g_attn[((size_t)((bh>>3)*NTOK+n))*DIMX+h*64+d]=s;
}

// ---- 10a. softmax over rows of 256 (sim1 in g_sim3, layout (bh,n,lm)) ----
__global__ void softmax1_kernel(){
    int w=threadIdx.x>>5, lane=threadIdx.x&31;
    size_t row=(size_t)blockIdx.x*8+w;
    float* p=g_sim3+row*ML;
    float4 v0=*(float4*)(p+lane*8);
    float4 v1=*(float4*)(p+lane*8+4);
    float mx=fmaxf(fmaxf(fmaxf(v0.x,v0.y),fmaxf(v0.z,v0.w)),
                   fmaxf(fmaxf(v1.x,v1.y),fmaxf(v1.z,v1.w)));
    #pragma unroll
    for(int o=16;o;o>>=1) mx=fmaxf(mx,__shfl_xor_sync(~0u,mx,o));
    v0.x=__expf(v0.x-mx); v0.y=__expf(v0.y-mx); v0.z=__expf(v0.z-mx); v0.w=__expf(v0.w-mx);
    v1.x=__expf(v1.x-mx); v1.y=__expf(v1.y-mx); v1.z=__expf(v1.z-mx); v1.w=__expf(v1.w-mx);
    float s=v0.x+v0.y+v0.z+v0.w+v1.x+v1.y+v1.z+v1.w;
    #pragma unroll
    for(int o=16;o;o>>=1) s+=__shfl_xor_sync(~0u,s,o);
    float inv=1.f/s;
    v0.x*=inv; v0.y*=inv; v0.z*=inv; v0.w*=inv;
    v1.x*=inv; v1.y*=inv; v1.z*=inv; v1.w*=inv;
    *(float4*)(p+lane*8)=v0;
    *(float4*)(p+lane*8+4)=v1;
}

// ---- 10b. g_attn += a1 @ Z2 (128x64) ----
__global__ void a1z2_kernel(){
    __shared__ float As[32][129], Bs[32][65];
    int bm=blockIdx.x*128, bh=blockIdx.y;
    const float* A=g_sim3+(size_t)bh*NTOK*ML;
    const float* Bp=g_Z2+(size_t)bh*ML*DH;
    int t=threadIdx.x, tx=t&15, ty=t>>4;
    float acc[8][4]={};
    for(int k0=0;k0<256;k0+=32){
        loadA_kmajor(As, A, ML, bm, k0, t);
        loadB_kn64(Bs, Bp, DH, 0, k0, t);
        __syncthreads();
        fma64(As,Bs,acc,tx,ty);
        __syncthreads();
    }
    int b=bh>>3, h=bh&7;
    #pragma unroll
    for(int i=0;i<8;i++){
        size_t base=((size_t)(b*NTOK+bm+ty*8+i))*DIMX+h*64;
        #pragma unroll
        for(int j=0;j<4;j++)
            g_attn[base+tx+(j<<4)]+=acc[i][j];
    }
}

// ---- 11. out = x + attn @ w_out + b_out (128x128) ----
__global__ void out_kernel(const float* __restrict__ W, const float* __restrict__ bias,
                           const float* __restrict__ x, float* __restrict__ out){
    __shared__ float As[32][129], Bs[32][129];
    int t=threadIdx.x, tx=t&15, ty=t>>4;
    int bn=blockIdx.x*128, bm=blockIdx.y*128;
    float acc[8][8]={};
    for(int k0=0;k0<512;k0+=32){
        loadA_kmajor(As, g_attn, DIMX, bm, k0, t);
        loadB_kn128(Bs, W, DIMX, bn, k0, t);
        __syncthreads();
        fma128(As,Bs,acc,tx,ty);
        __syncthreads();
    }
    #pragma unroll
    for(int i=0;i<8;i++){
        size_t r=(size_t)(bm+ty*8+i)*DIMX;
        #pragma unroll
        for(int j=0;j<8;j++){
            int col=bn+tx+(j<<4);
            out[r+col]=x[r+col]+bias[col]+acc[i][j];
        }
    }
}

extern "C" void kernel_launch(void* const* d_in, const int* in_sizes, int n_in,
                              void* d_out, int out_size){
    const float* x    = (const float*)d_in[0];
    const float* ln_w = (const float*)d_in[2];
    const float* ln_b = (const float*)d_in[3];
    const float* wqkv = (const float*)d_in[4];
    const float* wout = (const float*)d_in[5];
    const float* bout = (const float*)d_in[6];
    const float* cw   = (const float*)d_in[7];
    float* out = (float*)d_out;

    float *z0,*z1,*a2p,*xz,*t1,*t2,*qlp,*klp,*qp,*kp,*sim3p;
    cudaGetSymbolAddress((void**)&z0, g_z0);
    cudaGetSymbolAddress((void**)&z1, g_z1);
    cudaGetSymbolAddress((void**)&a2p, g_a2);
    cudaGetSymbolAddress((void**)&xz, g_xz);
    cudaGetSymbolAddress((void**)&t1, g_t1);
    cudaGetSymbolAddress((void**)&t2, g_t2);
    cudaGetSymbolAddress((void**)&qlp, g_ql);
    cudaGetSymbolAddress((void**)&klp, g_kl);
    cudaGetSymbolAddress((void**)&qp, g_q);
    cudaGetSymbolAddress((void**)&kp, g_k);
    cudaGetSymbolAddress((void**)&sim3p, g_sim3);

    ln_kernel<<<BB*NTOK, 256>>>(x, ln_w, ln_b);
    qkv_kernel<<<dim3(12,128), 256>>>(wqkv);
    landmark_kernel<<<BHN*ML, 64>>>();
    a2_kernel<<<dim3(BHN,32), 256>>>();
    scal_reset_kernel<<<1,1>>>();
    pinv_sums_kernel<<<BHN, 256>>>();
    zinit_kernel<<<4096, 256>>>();

    float* zc=z0; float* za=z1;
    for(int it=0; it<6; it++){
        mm256_kernel<<<dim3(BHN,4,4),256>>>(a2p, zc, xz, 0.f, -1.f);
        mm256_kernel<<<dim3(BHN,4,4),256>>>(xz, xz, t1, 7.f, 1.f);
        mm256_kernel<<<dim3(BHN,4,4),256>>>(xz, t1, t2, 15.f, 1.f);
        mm256_kernel<<<dim3(BHN,4,4),256>>>(zc, t2, za, 13.f, 0.25f);
        float* tmp=zc; zc=za; za=tmp;
    }
    // zc == z0 after 6 swaps

    // sim3 = ql @ k^T : (bh, 256 x 8192)
    sim_kernel<<<dim3(64,2,BHN), 256>>>(qlp, kp, sim3p,
        (size_t)ML*DH, (size_t)NTOK*DH, (size_t)ML*NTOK, NTOK);
    softmax3_kernel<<<BHN*ML, 256>>>();
    a3v_kernel<<<dim3(8,2,BHN), 256>>>();
    a3v_reduce_kernel<<<1024, 256>>>();
    z2_kernel<<<dim3(2,BHN), 256>>>();
    conv_kernel<<<32768, 256>>>(cw);

    // sim1 = q @ kl^T : (bh, 8192 x 256), reuse g_sim3
    sim_kernel<<<dim3(2,64,BHN), 256>>>(qp, klp, sim3p,
        (size_t)NTOK*DH, (size_t)ML*DH, (size_t)NTOK*ML, ML);
    softmax1_kernel<<<BHN*NTOK/8, 256>>>();
    a1z2_kernel<<<dim3(64,BHN), 256>>>();
    out_kernel<<<dim3(4,128), 256>>>(wout, bout, x, out);
}